// round 13
// baseline (speedup 1.0000x reference)
#include <cuda_runtime.h>

#define NB   32768
#define NCO  64
#define NDG  2048
#define NCA  256
#define KACT 81
#define MR   32
#define NTHR 512
#define STR  36   // float stride of [256 col][32 row] tiles (4-way max STS conflict)

typedef unsigned long long u64;

// ---------------- device-global scratch ----------------
__device__ float4 g_Wpp4[16 * NDG];      // [k4][c]
__device__ float  g_WmossyT[NDG * NCA];  // [d][c]
__device__ float4 g_Wrec4[64 * NCA];     // [j4][c], pre-scaled by 1.4 (=2*GAIN)
__device__ float4 g_Wcssc4[64 * NCA];    // (Wcs @ Wsc)
__device__ float4 g_Wogsc4[64 * NCA];    // 2*(Wog @ Wsc)
__device__ float4 g_Wogta4[16 * NCA];    // 2*(Wog @ Wta)
__device__ float4 g_Wcdta4[16 * NCA];    // (Wcd @ Wta)
__device__ float  g_btap[NCA];           // Wcd @ b_ta
__device__ float  g_bcssc[NCA];          // Wcs @ b_sc
__device__ float  g_b2ogta[NCA];         // 2*(Wog @ b_ta) + 2*b_og
__device__ float  g_b2ogsc[NCA];         // 2*(Wog @ b_sc) + 2*b_og
__device__ float  g_part[256 * NCO];

// ---------------- f32x2 packed helpers ----------------
__device__ __forceinline__ u64 pk2(float v){
    u64 r; asm("mov.b64 %0, {%1, %1};" : "=l"(r) : "f"(v)); return r;
}
__device__ __forceinline__ void upk(u64 p, float& a, float& b){
    asm("mov.b64 {%0, %1}, %2;" : "=f"(a), "=f"(b) : "l"(p));
}
__device__ __forceinline__ void fma2(u64& acc, u64 v, u64 w){
    asm("fma.rn.f32x2 %0, %1, %2, %0;" : "+l"(acc) : "l"(v), "l"(w));
}

// order-preserving float->uint key
__device__ __forceinline__ unsigned f2u(float f){
    unsigned u = __float_as_uint(f);
    return u ^ ((u & 0x80000000u) ? 0xFFFFFFFFu : 0x80000000u);
}

// tanh where z = 2x is already applied
__device__ __forceinline__ float fast_tanh_z(float z){
    float e = __expf(z);
    return 1.f - __fdividef(2.f, e + 1.f);
}

// 2 cols x 8 rows packed: acc[0..3]=colA row-pairs, acc[4..7]=colB
__device__ __forceinline__ void fma2x8_u(u64 acc[8], const float* __restrict__ sT,
                                         u64 wA, u64 wB){
    const ulonglong2* e = (const ulonglong2*)sT;
    ulonglong2 v0 = e[0], v1 = e[1];
    fma2(acc[0], v0.x, wA); fma2(acc[1], v0.y, wA);
    fma2(acc[2], v1.x, wA); fma2(acc[3], v1.y, wA);
    fma2(acc[4], v0.x, wB); fma2(acc[5], v0.y, wB);
    fma2(acc[6], v1.x, wB); fma2(acc[7], v1.y, wB);
}

__device__ __forceinline__ void fma2x8_pair_u(u64 P[8], u64 Q[8],
                                              const float* __restrict__ sT,
                                              u64 pA, u64 pB, u64 qA, u64 qB){
    const ulonglong2* e = (const ulonglong2*)sT;
    ulonglong2 v0 = e[0], v1 = e[1];
    fma2(P[0], v0.x, pA); fma2(P[1], v0.y, pA);
    fma2(P[2], v1.x, pA); fma2(P[3], v1.y, pA);
    fma2(P[4], v0.x, pB); fma2(P[5], v0.y, pB);
    fma2(P[6], v1.x, pB); fma2(P[7], v1.y, pB);
    fma2(Q[0], v0.x, qA); fma2(Q[1], v0.y, qA);
    fma2(Q[2], v1.x, qA); fma2(Q[3], v1.y, qA);
    fma2(Q[4], v0.x, qB); fma2(Q[5], v0.y, qB);
    fma2(Q[6], v1.x, qB); fma2(Q[7], v1.y, qB);
}

// GEMV over 256 inputs (buffers stride STR)
__device__ __forceinline__ void gemv256_u(u64 acc[8], const float* __restrict__ src,
                                          const float4* __restrict__ w4, int c0, int rb){
    #pragma unroll 4
    for (int j4 = 0; j4 < 64; ++j4){
        float4 wa = w4[j4 * NCA + c0];
        float4 wb = w4[j4 * NCA + c0 + 128];
        fma2x8_u(acc, src + (4*j4+0)*STR + rb, pk2(wa.x), pk2(wb.x));
        fma2x8_u(acc, src + (4*j4+1)*STR + rb, pk2(wa.y), pk2(wb.y));
        fma2x8_u(acc, src + (4*j4+2)*STR + rb, pk2(wa.z), pk2(wb.z));
        fma2x8_u(acc, src + (4*j4+3)*STR + rb, pk2(wa.w), pk2(wb.w));
    }
}

__device__ __forceinline__ void gemv256_pair_u(u64 P[8], u64 Q[8],
                                               const float* __restrict__ src,
                                               const float4* __restrict__ wp,
                                               const float4* __restrict__ wq,
                                               int c0, int rb){
    #pragma unroll 2
    for (int j4 = 0; j4 < 64; ++j4){
        float4 pa = wp[j4 * NCA + c0];
        float4 pb = wp[j4 * NCA + c0 + 128];
        float4 qa = wq[j4 * NCA + c0];
        float4 qb = wq[j4 * NCA + c0 + 128];
        fma2x8_pair_u(P, Q, src + (4*j4+0)*STR + rb, pk2(pa.x), pk2(pb.x), pk2(qa.x), pk2(qb.x));
        fma2x8_pair_u(P, Q, src + (4*j4+1)*STR + rb, pk2(pa.y), pk2(pb.y), pk2(qa.y), pk2(qb.y));
        fma2x8_pair_u(P, Q, src + (4*j4+2)*STR + rb, pk2(pa.z), pk2(pb.z), pk2(qa.z), pk2(qb.z));
        fma2x8_pair_u(P, Q, src + (4*j4+3)*STR + rb, pk2(pa.w), pk2(pb.w), pk2(qa.w), pk2(qb.w));
    }
}

// paired GEMV over 64 inputs (reads s_ecT [64][32])
__device__ __forceinline__ void gemv64_pair_u(u64 P[8], u64 Q[8],
                                              const float* __restrict__ src,
                                              const float4* __restrict__ wp,
                                              const float4* __restrict__ wq,
                                              int c0, int rb){
    #pragma unroll 2
    for (int k4 = 0; k4 < 16; ++k4){
        float4 pa = wp[k4 * NCA + c0];
        float4 pb = wp[k4 * NCA + c0 + 128];
        float4 qa = wq[k4 * NCA + c0];
        float4 qb = wq[k4 * NCA + c0 + 128];
        fma2x8_pair_u(P, Q, src + (4*k4+0)*32 + rb, pk2(pa.x), pk2(pb.x), pk2(qa.x), pk2(qb.x));
        fma2x8_pair_u(P, Q, src + (4*k4+1)*32 + rb, pk2(pa.y), pk2(pb.y), pk2(qa.y), pk2(qb.y));
        fma2x8_pair_u(P, Q, src + (4*k4+2)*32 + rb, pk2(pa.z), pk2(pb.z), pk2(qa.z), pk2(qb.z));
        fma2x8_pair_u(P, Q, src + (4*k4+3)*32 + rb, pk2(pa.w), pk2(pb.w), pk2(qa.w), pk2(qb.w));
    }
}

__device__ __forceinline__ void store2x8(float* __restrict__ dst, const float acc[16],
                                         int c0, int rb){
    float4* d0 = (float4*)(dst + c0*STR + rb);
    float4* d1 = (float4*)(dst + (c0+128)*STR + rb);
    d0[0] = make_float4(acc[0], acc[1], acc[2], acc[3]);
    d0[1] = make_float4(acc[4], acc[5], acc[6], acc[7]);
    d1[0] = make_float4(acc[8], acc[9], acc[10], acc[11]);
    d1[1] = make_float4(acc[12], acc[13], acc[14], acc[15]);
}

// unpack 8 packed accs (2col x 8row): [0..7]=colA rows, [8..15]=colB rows
__device__ __forceinline__ void upk8(const u64 acc[8], float out[16]){
    upk(acc[0], out[0],  out[1]);  upk(acc[1], out[2],  out[3]);
    upk(acc[2], out[4],  out[5]);  upk(acc[3], out[6],  out[7]);
    upk(acc[4], out[8],  out[9]);  upk(acc[5], out[10], out[11]);
    upk(acc[6], out[12], out[13]); upk(acc[7], out[14], out[15]);
}

// ---------------- prep kernel (unchanged from R12) ----------------
__global__ void prep_kernel(const float* __restrict__ coords,
                            const float* __restrict__ W_pp, const float* __restrict__ W_mo,
                            const float* __restrict__ W_rec)
{
    __shared__ float sh[32 * 65];
    const int b = blockIdx.x, tid = threadIdx.x;
    const int tx = tid & 31, ty = tid >> 5;

    if (b < 256){
        __shared__ float s[4][64];
        int c = tid & 63, g = tid >> 6;
        int r0 = b * 128 + g * 32;
        float acc = 0.f;
        #pragma unroll 8
        for (int i = 0; i < 32; ++i) acc += coords[(r0 + i) * 64 + c];
        s[g][c] = acc;
        __syncthreads();
        if (g == 0) g_part[b * 64 + c] = s[0][c] + s[1][c] + s[2][c] + s[3][c];
    } else if (b < 768){
        int b2 = b - 256;
        int ci = b2 & 7, di = b2 >> 3;
        #pragma unroll
        for (int i = 0; i < 4; ++i){
            int cc = ty + 8 * i;
            sh[cc * 33 + tx] = W_mo[(ci * 32 + cc) * 2048 + di * 32 + tx];
        }
        __syncthreads();
        #pragma unroll
        for (int i = 0; i < 4; ++i){
            int dd = ty + 8 * i;
            g_WmossyT[(di * 32 + dd) * 256 + ci * 32 + tx] = sh[tx * 33 + dd];
        }
    } else if (b < 832){
        int c0 = (b - 768) * 32;
        #pragma unroll
        for (int i = 0; i < 8; ++i){
            int idx = i * 256 + tid;
            int row = idx >> 6, col = idx & 63;
            sh[row * 65 + col] = W_pp[(c0 + row) * 64 + col];
        }
        __syncthreads();
        #pragma unroll
        for (int oi = 0; oi < 2; ++oi){
            int idx = oi * 256 + tid;
            int k4 = idx >> 5, c = idx & 31;
            float4 v = make_float4(sh[c * 65 + 4*k4], sh[c * 65 + 4*k4 + 1],
                                   sh[c * 65 + 4*k4 + 2], sh[c * 65 + 4*k4 + 3]);
            g_Wpp4[k4 * NDG + c0 + c] = v;
        }
    } else {
        int b4 = b - 832;
        int ci = b4 & 7, ji = b4 >> 3;
        #pragma unroll
        for (int i = 0; i < 4; ++i){
            int cc = ty + 8 * i;
            sh[cc * 33 + tx] = W_rec[(ci * 32 + cc) * 256 + ji * 32 + tx];
        }
        __syncthreads();
        {
            int j4l = ty, c = tx;
            float4 v = make_float4(1.4f * sh[c * 33 + 4*j4l],     1.4f * sh[c * 33 + 4*j4l + 1],
                                   1.4f * sh[c * 33 + 4*j4l + 2], 1.4f * sh[c * 33 + 4*j4l + 3]);
            g_Wrec4[(ji * 8 + j4l) * NCA + ci * 32 + c] = v;
        }
    }
}

// ---------------- tiled GEMM prep + bias dots (unchanged) ----------------
__global__ void prep_gemm(const float* __restrict__ W_cs, const float* __restrict__ W_cd,
                          const float* __restrict__ W_og,
                          const float* __restrict__ W_sc, const float* __restrict__ W_ta,
                          const float* __restrict__ b_ta, const float* __restrict__ b_sc,
                          const float* __restrict__ b_og)
{
    int b = blockIdx.x;
    int tx = threadIdx.x & 31;
    int ty = threadIdx.x >> 5;

    if (b >= 160){
        int t = b - 160;
        const float* A   = (t==0) ? W_cd : (t==1) ? W_cs : W_og;
        const float* vec = (t==0) ? b_ta : (t==1) ? b_sc : (t==2) ? b_ta : b_sc;
        float* dst = (t==0) ? g_btap : (t==1) ? g_bcssc : (t==2) ? g_b2ogta : g_b2ogsc;
        float scale = (t < 2) ? 1.f : 2.f;
        for (int c = ty; c < 256; c += 8){
            float acc = 0.f;
            #pragma unroll
            for (int kt = 0; kt < 8; ++kt)
                acc = fmaf(A[c * 256 + kt * 32 + tx], vec[kt * 32 + tx], acc);
            #pragma unroll
            for (int o = 16; o; o >>= 1) acc += __shfl_xor_sync(~0u, acc, o);
            if (tx == 0) dst[c] = scale * acc + ((t >= 2) ? 2.f * b_og[c] : 0.f);
        }
        return;
    }

    __shared__ float As[32][33];
    __shared__ float Bs[32][33];

    const float *A, *B; float* dst; float scale; int ldb, jtiles;
    if (b < 64)      { A = W_cs; B = W_sc; dst = (float*)g_Wcssc4; scale = 1.f; ldb = 256; jtiles = 8; }
    else if (b < 128){ A = W_og; B = W_sc; dst = (float*)g_Wogsc4; scale = 2.f; ldb = 256; jtiles = 8; b -= 64; }
    else if (b < 144){ A = W_og; B = W_ta; dst = (float*)g_Wogta4; scale = 2.f; ldb = 64;  jtiles = 2; b -= 128; }
    else             { A = W_cd; B = W_ta; dst = (float*)g_Wcdta4; scale = 1.f; ldb = 64;  jtiles = 2; b -= 144; }

    int ci = b / jtiles, ji = b % jtiles;
    float acc[4] = {0.f, 0.f, 0.f, 0.f};
    for (int kt = 0; kt < 8; ++kt){
        #pragma unroll
        for (int ii = 0; ii < 4; ++ii){
            int rr = ty + 8 * ii;
            As[rr][tx] = A[(ci * 32 + rr) * 256 + kt * 32 + tx];
            Bs[rr][tx] = B[(kt * 32 + rr) * ldb + ji * 32 + tx];
        }
        __syncthreads();
        #pragma unroll
        for (int kk = 0; kk < 32; ++kk){
            float bv = Bs[kk][tx];
            #pragma unroll
            for (int ii = 0; ii < 4; ++ii)
                acc[ii] = fmaf(As[ty + 8 * ii][kk], bv, acc[ii]);
        }
        __syncthreads();
    }

    #pragma unroll
    for (int ii = 0; ii < 4; ++ii)
        As[ty + 8 * ii][tx] = scale * acc[ii];
    __syncthreads();
    {
        int j4l = ty, cl = tx;
        int j0 = ji * 32 + j4l * 4;
        float4 v = make_float4(As[cl][j4l*4], As[cl][j4l*4+1], As[cl][j4l*4+2], As[cl][j4l*4+3]);
        ((float4*)dst)[(j0 >> 2) * NCA + ci * 32 + cl] = v;
    }
}

// ---------------- fused pipeline: 32 rows per block, 512 threads, 1 block/SM ----------------
extern "C" __global__ void __launch_bounds__(NTHR, 1)
fused_kernel(const float* __restrict__ coords,
             const float* __restrict__ ec_g,  const float* __restrict__ ec_b,
             const float* __restrict__ b_pp,
             const float* __restrict__ dg_g,  const float* __restrict__ dg_b,
             float* __restrict__ out)
{
    extern __shared__ float sm[];
    float*    B1       = sm;                      // [256][36]
    float*    B2       = sm + 9216;
    float*    B3       = sm + 18432;
    float*    pool     = sm;                      // union (pool 16x2048 = 32768)
    float*    s_ecT    = sm + 32768;              // [64][32] = 2048
    float2*   s_act    = (float2*)(sm + 34816);   // 32 x 84 float2 = 5376 floats
    unsigned* s_hist   = (unsigned*)(sm + 40192); // 16 x 256 = 4096
    float*    s_bufadd = sm + 44288;              // 64
    float*    s_nov    = sm + 44352;              // 32
    float*    s_red    = sm + 44384;              // 16 warps x 24 = 384

    const int tid  = threadIdx.x;
    const int w    = tid >> 5;
    const int lane = tid & 31;
    const unsigned lmask = (1u << lane) - 1u;
    const int row0 = blockIdx.x * MR;
    const int c0   = tid & 127;          // col pair (c0, c0+128)
    const int rb   = (tid >> 7) * 8;     // row group (0, 8, 16, 24)

    // ---- Stage 0: reduce column partials -> s_bufadd (stage through pool) ----
    {
        int c = tid & 63, q = tid >> 6;   // q 0..7
        float a = 0.f;
        #pragma unroll 8
        for (int i = 0; i < 32; ++i) a += g_part[(q * 32 + i) * 64 + c];
        pool[q * 64 + c] = a;
        __syncthreads();
        if (tid < 64){
            float s = 0.f;
            #pragma unroll
            for (int qq = 0; qq < 8; ++qq) s += pool[qq * 64 + tid];
            s_bufadd[tid] = (0.05f / (float)NB) * s;
        }
        __syncthreads();
    }

    // ---- Stage 1: EC layernorm (2 rows/warp) -> s_ecT[64][32] ----
    for (int rr = 0; rr < 2; ++rr){
        int r  = w * 2 + rr;
        int gr = row0 + r;
        float v1 = coords[gr*64 + lane]      + s_bufadd[lane];
        float v2 = coords[gr*64 + lane + 32] + s_bufadd[lane + 32];
        float s = v1 + v2, s2 = v1*v1 + v2*v2;
        #pragma unroll
        for (int o = 16; o; o >>= 1){ s += __shfl_xor_sync(~0u, s, o); s2 += __shfl_xor_sync(~0u, s2, o); }
        float mu = s * (1.f/64.f);
        float rs = rsqrtf(s2 * (1.f/64.f) - mu*mu + 1e-5f);
        s_ecT[lane*32 + r]      = (v1 - mu) * rs * ec_g[lane]      + ec_b[lane];
        s_ecT[(lane+32)*32 + r] = (v2 - mu) * rs * ec_g[lane + 32] + ec_b[lane + 32];
    }
    __syncthreads();

    // ---- Stages 2-4: two passes of 16 rows: proj GEMM + LN + 3-pass radix top-81 ----
    for (int p = 0; p < 2; ++p){
        // proj: thread owns col c (4 iterations), 16 rows packed as 8 u64
        for (int nt = 0; nt < 4; ++nt){
            int c = nt * 512 + tid;
            u64 acc[8];
            u64 bp = pk2(b_pp[c]);
            #pragma unroll
            for (int q = 0; q < 8; ++q) acc[q] = bp;
            #pragma unroll 4
            for (int k4 = 0; k4 < 16; ++k4){
                float4 wv = g_Wpp4[k4 * NDG + c];
                #pragma unroll
                for (int jj = 0; jj < 4; ++jj){
                    const ulonglong2* e = (const ulonglong2*)(s_ecT + (4*k4+jj)*32 + p*16);
                    ulonglong2 v0 = e[0], v1 = e[1], v2 = e[2], v3 = e[3];
                    float wk = jj==0?wv.x:jj==1?wv.y:jj==2?wv.z:wv.w;
                    u64 w2 = pk2(wk);
                    fma2(acc[0], v0.x, w2); fma2(acc[1], v0.y, w2);
                    fma2(acc[2], v1.x, w2); fma2(acc[3], v1.y, w2);
                    fma2(acc[4], v2.x, w2); fma2(acc[5], v2.y, w2);
                    fma2(acc[6], v3.x, w2); fma2(acc[7], v3.y, w2);
                }
            }
            float f[16];
            upk8(acc, f);   // here [0..15] are rows 0..15 directly (single col)
            #pragma unroll
            for (int i = 0; i < 16; ++i)
                pool[i*NDG + c] = fmaxf(f[i], 0.f);
        }
        __syncthreads();

        // 1 row per warp (16 warps = 16 rows): LN + 3-pass radix + compaction
        {
            unsigned* hist = s_hist + w * 256;
            int rg  = p * 16 + w;
            float* row = pool + w * NDG;
            float s = 0.f, s2 = 0.f;
            for (int i = lane; i < NDG; i += 32){ float v = row[i]; s += v; s2 += v*v; }
            #pragma unroll
            for (int o = 16; o; o >>= 1){ s += __shfl_xor_sync(~0u, s, o); s2 += __shfl_xor_sync(~0u, s2, o); }
            float mu = s * (1.f/2048.f);
            float rs = rsqrtf(s2 * (1.f/2048.f) - mu*mu + 1e-5f);
            for (int i = lane; i < NDG; i += 32)
                row[i] = (row[i] - mu) * rs * dg_g[i] + dg_b[i];
            __syncwarp();

            unsigned prefix = 0; int need = KACT;
            for (int pp = 3; pp >= 1; --pp){
                for (int b = lane; b < 256; b += 32) hist[b] = 0;
                __syncwarp();
                unsigned himask = (pp == 3) ? 0u : (0xFFFFFFFFu << ((pp + 1) * 8));
                for (int i = lane; i < NDG; i += 32){
                    unsigned uu = f2u(row[i]);
                    if ((uu & himask) == prefix) atomicAdd(&hist[(uu >> (pp*8)) & 255], 1u);
                }
                __syncwarp();
                int b0 = 255 - lane * 8;
                unsigned cs[8]; unsigned cnt = 0;
                #pragma unroll
                for (int t = 0; t < 8; ++t){ cs[t] = hist[b0 - t]; cnt += cs[t]; }
                unsigned inc = cnt;
                #pragma unroll
                for (int o = 1; o < 32; o <<= 1){ unsigned v = __shfl_up_sync(~0u, inc, o); if (lane >= o) inc += v; }
                unsigned excl = inc - cnt;
                bool hit = (excl < (unsigned)need) && ((unsigned)need <= inc);
                unsigned bal = __ballot_sync(~0u, hit);
                int srcl = __ffs(bal) - 1;
                int selbin = 0, newneed = 0, found = 0;
                if (hit){
                    unsigned cum = excl;
                    #pragma unroll
                    for (int t = 0; t < 8; ++t){
                        unsigned nc = cum + cs[t];
                        if (!found && nc >= (unsigned)need){ selbin = b0 - t; newneed = need - (int)cum; found = 1; }
                        cum = nc;
                    }
                }
                selbin = __shfl_sync(~0u, selbin, srcl);
                need   = __shfl_sync(~0u, newneed, srcl);
                prefix |= ((unsigned)selbin) << (pp * 8);
            }

            int base = 0, ties = 0;
            for (int g = 0; g < 64; ++g){
                int c = g * 32 + lane;
                float v = row[c];
                unsigned uu = f2u(v) & 0xFFFFFF00u;
                bool eq = (uu == prefix);
                bool gt = (uu >  prefix);
                unsigned beq = __ballot_sync(~0u, eq);
                int tr = ties + __popc(beq & lmask);
                bool act = gt || (eq && tr < need);
                unsigned ba = __ballot_sync(~0u, act);
                if (act){
                    int pos = base + __popc(ba & lmask);
                    s_act[rg*84 + pos] = make_float2(v, __int_as_float(c << 8));
                }
                base += __popc(ba);
                ties += __popc(beq);
            }
        }
        __syncthreads();
    }

    // ---- Stage 5: cue = sparse(dg) @ WmossyT -> B1[256][STR] ----
    {
        int c  = tid & 255;
        int rh = (tid >> 8) * 16;   // rows rh..rh+15
        float acc[16];
        #pragma unroll
        for (int r = 0; r < 16; ++r) acc[r] = 0.f;
        #pragma unroll 2
        for (int a = 0; a < KACT; ++a){
            #pragma unroll
            for (int r = 0; r < 16; ++r){
                float2 pv = s_act[(rh + r)*84 + a];
                acc[r] = fmaf(pv.x, g_WmossyT[__float_as_int(pv.y) + c], acc[r]);
            }
        }
        float4* dp = (float4*)(B1 + c*STR + rh);
        dp[0] = make_float4(acc[0], acc[1], acc[2], acc[3]);
        dp[1] = make_float4(acc[4], acc[5], acc[6], acc[7]);
        dp[2] = make_float4(acc[8], acc[9], acc[10], acc[11]);
        dp[3] = make_float4(acc[12], acc[13], acc[14], acc[15]);
    }
    __syncthreads();

    // ---- Stage 6: 5-step settle ----
    float cuev[16];
    {
        const float4* ca = (const float4*)(B1 + c0*STR + rb);
        const float4* cb = (const float4*)(B1 + (c0+128)*STR + rb);
        float4 x0 = ca[0], x1 = ca[1], y0 = cb[0], y1 = cb[1];
        cuev[0]=0.6f*x0.x; cuev[1]=0.6f*x0.y; cuev[2]=0.6f*x0.z; cuev[3]=0.6f*x0.w;
        cuev[4]=0.6f*x1.x; cuev[5]=0.6f*x1.y; cuev[6]=0.6f*x1.z; cuev[7]=0.6f*x1.w;
        cuev[8]=0.6f*y0.x; cuev[9]=0.6f*y0.y; cuev[10]=0.6f*y0.z; cuev[11]=0.6f*y0.w;
        cuev[12]=0.6f*y1.x; cuev[13]=0.6f*y1.y; cuev[14]=0.6f*y1.z; cuev[15]=0.6f*y1.w;
    }
    const float* cur = B1;
    float* nxt = B2;
    for (int it = 0; it < 5; ++it){
        u64 acc[8];
        #pragma unroll
        for (int q = 0; q < 8; ++q) acc[q] = 0ull;
        gemv256_u(acc, cur, g_Wrec4, c0, rb);
        float z[16];
        upk8(acc, z);
        float res[16];
        #pragma unroll
        for (int r = 0; r < 16; ++r) res[r] = fast_tanh_z(z[r] + cuev[r]);
        store2x8(nxt, res, c0, rb);
        __syncthreads();
        if (it == 0){ cur = B2; nxt = B3; }
        else { float* t = (float*)cur; cur = nxt; nxt = t; }
    }
    // final state in B2

    // ---- Stages 8+10 fused: 4 GEMVs in 2 paired passes ----
    float fA[16], fB[16];
    {
        u64 acc_s[8], accB[8];
        {
            u64 sa = pk2(g_bcssc[c0]),  sb = pk2(g_bcssc[c0 + 128]);
            u64 oa = pk2(g_b2ogsc[c0]), ob = pk2(g_b2ogsc[c0 + 128]);
            #pragma unroll
            for (int q = 0; q < 4; ++q){
                acc_s[q] = sa; acc_s[q+4] = sb;
                accB[q]  = oa; accB[q+4]  = ob;
            }
        }
        gemv256_pair_u(acc_s, accB, B2, g_Wcssc4, g_Wogsc4, c0, rb);

        u64 acc_d[8], accA[8];
        {
            u64 da = pk2(g_btap[c0]),   db = pk2(g_btap[c0 + 128]);
            u64 oa = pk2(g_b2ogta[c0]), ob = pk2(g_b2ogta[c0 + 128]);
            #pragma unroll
            for (int q = 0; q < 4; ++q){
                acc_d[q] = da; acc_d[q+4] = db;
                accA[q]  = oa; accA[q+4]  = ob;
            }
        }
        gemv64_pair_u(acc_d, accA, s_ecT, g_Wcdta4, g_Wogta4, c0, rb);

        float fs[16], fd[16];
        upk8(acc_s, fs); upk8(acc_d, fd);
        upk8(accA, fA);  upk8(accB, fB);

        #pragma unroll
        for (int i = 0; i < 8; ++i){
            float sd = fs[i]*fd[i] + fs[i+8]*fd[i+8];
            float sn = fs[i]*fs[i] + fs[i+8]*fs[i+8];
            float dn = fd[i]*fd[i] + fd[i+8]*fd[i+8];
            #pragma unroll
            for (int o = 16; o; o >>= 1){
                sd += __shfl_xor_sync(~0u, sd, o);
                sn += __shfl_xor_sync(~0u, sn, o);
                dn += __shfl_xor_sync(~0u, dn, o);
            }
            if (lane == 0){
                s_red[w*24 + i*3 + 0] = sd;
                s_red[w*24 + i*3 + 1] = sn;
                s_red[w*24 + i*3 + 2] = dn;
            }
        }
    }
    __syncthreads();
    if (tid < 32){
        int r = tid, rl = r & 7, wb = (r >> 3) * 4;
        float sd = 0.f, sn = 0.f, dn = 0.f;
        #pragma unroll
        for (int q = 0; q < 4; ++q){
            sd += s_red[(wb+q)*24 + rl*3 + 0];
            sn += s_red[(wb+q)*24 + rl*3 + 1];
            dn += s_red[(wb+q)*24 + rl*3 + 2];
        }
        float s_n = fmaxf(sqrtf(sn), 1e-8f);
        float d_n = fmaxf(sqrtf(dn), 1e-8f);
        float cosv = sd / (s_n * d_n);
        float nov = fminf(fmaxf(1.f - cosv, 0.f), 1.f);
        s_nov[r] = nov;
        out[(long long)NB * NCA + row0 + r] = nov;
    }
    __syncthreads();

    // ---- epilogue: out = tanh( g*A + (1-g)*B ) ----
    {
        float4 g0 = *(const float4*)(s_nov + rb);
        float4 g1 = *(const float4*)(s_nov + rb + 4);
        float gts[8] = {g0.x, g0.y, g0.z, g0.w, g1.x, g1.y, g1.z, g1.w};
        #pragma unroll
        for (int i = 0; i < 8; ++i){
            float g = gts[i];
            float za = fmaf(g, fA[i],   (1.f - g) * fB[i]);
            float zb = fmaf(g, fA[i+8], (1.f - g) * fB[i+8]);
            out[(long long)(row0 + rb + i) * NCA + c0]       = fast_tanh_z(za);
            out[(long long)(row0 + rb + i) * NCA + c0 + 128] = fast_tanh_z(zb);
        }
    }
}

// ---------------- launch ----------------
extern "C" void kernel_launch(void* const* d_in, const int* in_sizes, int n_in,
                              void* d_out, int out_size)
{
    const float* coords = (const float*)d_in[0];
    const float* ec_g   = (const float*)d_in[1];
    const float* ec_b   = (const float*)d_in[2];
    const float* W_pp   = (const float*)d_in[3];
    const float* b_pp   = (const float*)d_in[4];
    const float* dg_g   = (const float*)d_in[5];
    const float* dg_b   = (const float*)d_in[6];
    const float* W_mo   = (const float*)d_in[7];
    const float* W_rec  = (const float*)d_in[8];
    const float* W_sc   = (const float*)d_in[9];
    const float* b_sc   = (const float*)d_in[10];
    const float* W_ta   = (const float*)d_in[11];
    const float* b_ta   = (const float*)d_in[12];
    const float* W_cs   = (const float*)d_in[13];
    const float* W_cd   = (const float*)d_in[14];
    const float* W_og   = (const float*)d_in[15];
    const float* b_og   = (const float*)d_in[16];
    float* out = (float*)d_out;

    // smem floats: union 32768 + ecT 2048 + act 5376 + hist 4096 + bufadd 64 + nov 32 + red 384
    const size_t smem = (size_t)(32768 + 2048 + 5376 + 4096 + 64 + 32 + 384) * 4;  // 179,072 B
    static int configured = 0;
    if (!configured){
        cudaFuncSetAttribute(fused_kernel, cudaFuncAttributeMaxDynamicSharedMemorySize, (int)smem);
        configured = 1;
    }

    prep_kernel<<<896, 256>>>(coords, W_pp, W_mo, W_rec);
    prep_gemm<<<164, 256>>>(W_cs, W_cd, W_og, W_sc, W_ta, b_ta, b_sc, b_og);
    fused_kernel<<<NB / MR, NTHR, smem>>>(coords, ec_g, ec_b, b_pp, dg_g, dg_b, out);
}

// round 15
// speedup vs baseline: 1.0700x; 1.0700x over previous
#include <cuda_runtime.h>

#define NB   32768
#define NCO  64
#define NDG  2048
#define NCA  256
#define KACT 81
#define MR   16
#define NTHR 256
#define STR  16   // float stride of [256 col][16 row] tiles

typedef unsigned long long u64;

// ---------------- device-global scratch ----------------
__device__ float4 g_Wpp4[16 * NDG];      // [k4][c]
__device__ float  g_WmossyT[NDG * NCA];  // [d][c]
__device__ float4 g_Wrec4[64 * NCA];     // [j4][c], pre-scaled by 1.4 (=2*GAIN)
__device__ float4 g_Wcssc4[64 * NCA];    // (Wcs @ Wsc)
__device__ float4 g_Wogsc4[64 * NCA];    // 2*(Wog @ Wsc)
__device__ float4 g_Wogta4[16 * NCA];    // 2*(Wog @ Wta)
__device__ float4 g_Wcdta4[16 * NCA];    // (Wcd @ Wta)
__device__ float  g_btap[NCA];           // Wcd @ b_ta
__device__ float  g_bcssc[NCA];          // Wcs @ b_sc
__device__ float  g_b2ogta[NCA];         // 2*(Wog @ b_ta) + 2*b_og
__device__ float  g_b2ogsc[NCA];         // 2*(Wog @ b_sc) + 2*b_og
__device__ float  g_part[256 * NCO];
__device__ float  g_scr[(long long)2048 * 8 * NDG];  // proj rows 8-15 spill (L2-resident)

// ---------------- f32x2 packed helpers ----------------
__device__ __forceinline__ u64 pk2(float v){
    u64 r; asm("mov.b64 %0, {%1, %1};" : "=l"(r) : "f"(v)); return r;
}
__device__ __forceinline__ void upk(u64 p, float& a, float& b){
    asm("mov.b64 {%0, %1}, %2;" : "=f"(a), "=f"(b) : "l"(p));
}
__device__ __forceinline__ void fma2(u64& acc, u64 v, u64 w){
    asm("fma.rn.f32x2 %0, %1, %2, %0;" : "+l"(acc) : "l"(v), "l"(w));
}

// order-preserving float->uint key
__device__ __forceinline__ unsigned f2u(float f){
    unsigned u = __float_as_uint(f);
    return u ^ ((u & 0x80000000u) ? 0xFFFFFFFFu : 0x80000000u);
}

// tanh where z = 2x is already applied
__device__ __forceinline__ float fast_tanh_z(float z){
    float e = __expf(z);
    return 1.f - __fdividef(2.f, e + 1.f);
}

// 2 cols x 8 rows packed: acc[0..3]=colA row-pairs, acc[4..7]=colB
__device__ __forceinline__ void fma2x8_u(u64 acc[8], const float* __restrict__ sT,
                                         u64 wA, u64 wB){
    const ulonglong2* e = (const ulonglong2*)sT;
    ulonglong2 v0 = e[0], v1 = e[1];
    fma2(acc[0], v0.x, wA); fma2(acc[1], v0.y, wA);
    fma2(acc[2], v1.x, wA); fma2(acc[3], v1.y, wA);
    fma2(acc[4], v0.x, wB); fma2(acc[5], v0.y, wB);
    fma2(acc[6], v1.x, wB); fma2(acc[7], v1.y, wB);
}

__device__ __forceinline__ void fma2x8_pair_u(u64 P[8], u64 Q[8],
                                              const float* __restrict__ sT,
                                              u64 pA, u64 pB, u64 qA, u64 qB){
    const ulonglong2* e = (const ulonglong2*)sT;
    ulonglong2 v0 = e[0], v1 = e[1];
    fma2(P[0], v0.x, pA); fma2(P[1], v0.y, pA);
    fma2(P[2], v1.x, pA); fma2(P[3], v1.y, pA);
    fma2(P[4], v0.x, pB); fma2(P[5], v0.y, pB);
    fma2(P[6], v1.x, pB); fma2(P[7], v1.y, pB);
    fma2(Q[0], v0.x, qA); fma2(Q[1], v0.y, qA);
    fma2(Q[2], v1.x, qA); fma2(Q[3], v1.y, qA);
    fma2(Q[4], v0.x, qB); fma2(Q[5], v0.y, qB);
    fma2(Q[6], v1.x, qB); fma2(Q[7], v1.y, qB);
}

// GEMV over 256 inputs
__device__ __forceinline__ void gemv256_u(u64 acc[8], const float* __restrict__ src,
                                          const float4* __restrict__ w4, int c0, int rb){
    #pragma unroll 4
    for (int j4 = 0; j4 < 64; ++j4){
        float4 wa = w4[j4 * NCA + c0];
        float4 wb = w4[j4 * NCA + c0 + 128];
        fma2x8_u(acc, src + (4*j4+0)*STR + rb, pk2(wa.x), pk2(wb.x));
        fma2x8_u(acc, src + (4*j4+1)*STR + rb, pk2(wa.y), pk2(wb.y));
        fma2x8_u(acc, src + (4*j4+2)*STR + rb, pk2(wa.z), pk2(wb.z));
        fma2x8_u(acc, src + (4*j4+3)*STR + rb, pk2(wa.w), pk2(wb.w));
    }
}

__device__ __forceinline__ void gemv256_pair_u(u64 P[8], u64 Q[8],
                                               const float* __restrict__ src,
                                               const float4* __restrict__ wp,
                                               const float4* __restrict__ wq,
                                               int c0, int rb){
    #pragma unroll 2
    for (int j4 = 0; j4 < 64; ++j4){
        float4 pa = wp[j4 * NCA + c0];
        float4 pb = wp[j4 * NCA + c0 + 128];
        float4 qa = wq[j4 * NCA + c0];
        float4 qb = wq[j4 * NCA + c0 + 128];
        fma2x8_pair_u(P, Q, src + (4*j4+0)*STR + rb, pk2(pa.x), pk2(pb.x), pk2(qa.x), pk2(qb.x));
        fma2x8_pair_u(P, Q, src + (4*j4+1)*STR + rb, pk2(pa.y), pk2(pb.y), pk2(qa.y), pk2(qb.y));
        fma2x8_pair_u(P, Q, src + (4*j4+2)*STR + rb, pk2(pa.z), pk2(pb.z), pk2(qa.z), pk2(qb.z));
        fma2x8_pair_u(P, Q, src + (4*j4+3)*STR + rb, pk2(pa.w), pk2(pb.w), pk2(qa.w), pk2(qb.w));
    }
}

// paired GEMV over 64 inputs (reads s_ecT [64][16])
__device__ __forceinline__ void gemv64_pair_u(u64 P[8], u64 Q[8],
                                              const float* __restrict__ src,
                                              const float4* __restrict__ wp,
                                              const float4* __restrict__ wq,
                                              int c0, int rb){
    #pragma unroll 2
    for (int k4 = 0; k4 < 16; ++k4){
        float4 pa = wp[k4 * NCA + c0];
        float4 pb = wp[k4 * NCA + c0 + 128];
        float4 qa = wq[k4 * NCA + c0];
        float4 qb = wq[k4 * NCA + c0 + 128];
        fma2x8_pair_u(P, Q, src + (4*k4+0)*16 + rb, pk2(pa.x), pk2(pb.x), pk2(qa.x), pk2(qb.x));
        fma2x8_pair_u(P, Q, src + (4*k4+1)*16 + rb, pk2(pa.y), pk2(pb.y), pk2(qa.y), pk2(qb.y));
        fma2x8_pair_u(P, Q, src + (4*k4+2)*16 + rb, pk2(pa.z), pk2(pb.z), pk2(qa.z), pk2(qb.z));
        fma2x8_pair_u(P, Q, src + (4*k4+3)*16 + rb, pk2(pa.w), pk2(pb.w), pk2(qa.w), pk2(qb.w));
    }
}

__device__ __forceinline__ void store2x8(float* __restrict__ dst, const float acc[16],
                                         int c0, int rb){
    float4* d0 = (float4*)(dst + c0*STR + rb);
    float4* d1 = (float4*)(dst + (c0+128)*STR + rb);
    d0[0] = make_float4(acc[0], acc[1], acc[2], acc[3]);
    d0[1] = make_float4(acc[4], acc[5], acc[6], acc[7]);
    d1[0] = make_float4(acc[8], acc[9], acc[10], acc[11]);
    d1[1] = make_float4(acc[12], acc[13], acc[14], acc[15]);
}

// unpack 8 packed accs: [0..7]=first set rows, [8..15]=second set rows
__device__ __forceinline__ void upk8(const u64 acc[8], float out[16]){
    upk(acc[0], out[0],  out[1]);  upk(acc[1], out[2],  out[3]);
    upk(acc[2], out[4],  out[5]);  upk(acc[3], out[6],  out[7]);
    upk(acc[4], out[8],  out[9]);  upk(acc[5], out[10], out[11]);
    upk(acc[6], out[12], out[13]); upk(acc[7], out[14], out[15]);
}

// ---------------- prep kernel: coalesced relayouts + column partial sums ----------------
__global__ void prep_kernel(const float* __restrict__ coords,
                            const float* __restrict__ W_pp, const float* __restrict__ W_mo,
                            const float* __restrict__ W_rec)
{
    __shared__ float sh[32 * 65];
    const int b = blockIdx.x, tid = threadIdx.x;
    const int tx = tid & 31, ty = tid >> 5;

    if (b < 256){
        __shared__ float s[4][64];
        int c = tid & 63, g = tid >> 6;
        int r0 = b * 128 + g * 32;
        float acc = 0.f;
        #pragma unroll 8
        for (int i = 0; i < 32; ++i) acc += coords[(r0 + i) * 64 + c];
        s[g][c] = acc;
        __syncthreads();
        if (g == 0) g_part[b * 64 + c] = s[0][c] + s[1][c] + s[2][c] + s[3][c];
    } else if (b < 768){
        int b2 = b - 256;
        int ci = b2 & 7, di = b2 >> 3;
        #pragma unroll
        for (int i = 0; i < 4; ++i){
            int cc = ty + 8 * i;
            sh[cc * 33 + tx] = W_mo[(ci * 32 + cc) * 2048 + di * 32 + tx];
        }
        __syncthreads();
        #pragma unroll
        for (int i = 0; i < 4; ++i){
            int dd = ty + 8 * i;
            g_WmossyT[(di * 32 + dd) * 256 + ci * 32 + tx] = sh[tx * 33 + dd];
        }
    } else if (b < 832){
        int c0 = (b - 768) * 32;
        #pragma unroll
        for (int i = 0; i < 8; ++i){
            int idx = i * 256 + tid;
            int row = idx >> 6, col = idx & 63;
            sh[row * 65 + col] = W_pp[(c0 + row) * 64 + col];
        }
        __syncthreads();
        #pragma unroll
        for (int oi = 0; oi < 2; ++oi){
            int idx = oi * 256 + tid;
            int k4 = idx >> 5, c = idx & 31;
            float4 v = make_float4(sh[c * 65 + 4*k4], sh[c * 65 + 4*k4 + 1],
                                   sh[c * 65 + 4*k4 + 2], sh[c * 65 + 4*k4 + 3]);
            g_Wpp4[k4 * NDG + c0 + c] = v;
        }
    } else {
        int b4 = b - 832;
        int ci = b4 & 7, ji = b4 >> 3;
        #pragma unroll
        for (int i = 0; i < 4; ++i){
            int cc = ty + 8 * i;
            sh[cc * 33 + tx] = W_rec[(ci * 32 + cc) * 256 + ji * 32 + tx];
        }
        __syncthreads();
        {
            int j4l = ty, c = tx;
            float4 v = make_float4(1.4f * sh[c * 33 + 4*j4l],     1.4f * sh[c * 33 + 4*j4l + 1],
                                   1.4f * sh[c * 33 + 4*j4l + 2], 1.4f * sh[c * 33 + 4*j4l + 3]);
            g_Wrec4[(ji * 8 + j4l) * NCA + ci * 32 + c] = v;
        }
    }
}

// ---------------- tiled GEMM prep + bias dots ----------------
__global__ void prep_gemm(const float* __restrict__ W_cs, const float* __restrict__ W_cd,
                          const float* __restrict__ W_og,
                          const float* __restrict__ W_sc, const float* __restrict__ W_ta,
                          const float* __restrict__ b_ta, const float* __restrict__ b_sc,
                          const float* __restrict__ b_og)
{
    int b = blockIdx.x;
    int tx = threadIdx.x & 31;
    int ty = threadIdx.x >> 5;

    if (b >= 160){
        int t = b - 160;
        const float* A   = (t==0) ? W_cd : (t==1) ? W_cs : W_og;
        const float* vec = (t==0) ? b_ta : (t==1) ? b_sc : (t==2) ? b_ta : b_sc;
        float* dst = (t==0) ? g_btap : (t==1) ? g_bcssc : (t==2) ? g_b2ogta : g_b2ogsc;
        float scale = (t < 2) ? 1.f : 2.f;
        for (int c = ty; c < 256; c += 8){
            float acc = 0.f;
            #pragma unroll
            for (int kt = 0; kt < 8; ++kt)
                acc = fmaf(A[c * 256 + kt * 32 + tx], vec[kt * 32 + tx], acc);
            #pragma unroll
            for (int o = 16; o; o >>= 1) acc += __shfl_xor_sync(~0u, acc, o);
            if (tx == 0) dst[c] = scale * acc + ((t >= 2) ? 2.f * b_og[c] : 0.f);
        }
        return;
    }

    __shared__ float As[32][33];
    __shared__ float Bs[32][33];

    const float *A, *B; float* dst; float scale; int ldb, jtiles;
    if (b < 64)      { A = W_cs; B = W_sc; dst = (float*)g_Wcssc4; scale = 1.f; ldb = 256; jtiles = 8; }
    else if (b < 128){ A = W_og; B = W_sc; dst = (float*)g_Wogsc4; scale = 2.f; ldb = 256; jtiles = 8; b -= 64; }
    else if (b < 144){ A = W_og; B = W_ta; dst = (float*)g_Wogta4; scale = 2.f; ldb = 64;  jtiles = 2; b -= 128; }
    else             { A = W_cd; B = W_ta; dst = (float*)g_Wcdta4; scale = 1.f; ldb = 64;  jtiles = 2; b -= 144; }

    int ci = b / jtiles, ji = b % jtiles;
    float acc[4] = {0.f, 0.f, 0.f, 0.f};
    for (int kt = 0; kt < 8; ++kt){
        #pragma unroll
        for (int ii = 0; ii < 4; ++ii){
            int rr = ty + 8 * ii;
            As[rr][tx] = A[(ci * 32 + rr) * 256 + kt * 32 + tx];
            Bs[rr][tx] = B[(kt * 32 + rr) * ldb + ji * 32 + tx];
        }
        __syncthreads();
        #pragma unroll
        for (int kk = 0; kk < 32; ++kk){
            float bv = Bs[kk][tx];
            #pragma unroll
            for (int ii = 0; ii < 4; ++ii)
                acc[ii] = fmaf(As[ty + 8 * ii][kk], bv, acc[ii]);
        }
        __syncthreads();
    }

    #pragma unroll
    for (int ii = 0; ii < 4; ++ii)
        As[ty + 8 * ii][tx] = scale * acc[ii];
    __syncthreads();
    {
        int j4l = ty, cl = tx;
        int j0 = ji * 32 + j4l * 4;
        float4 v = make_float4(As[cl][j4l*4], As[cl][j4l*4+1], As[cl][j4l*4+2], As[cl][j4l*4+3]);
        ((float4*)dst)[(j0 >> 2) * NCA + ci * 32 + cl] = v;
    }
}

// ---------------- fused pipeline: 16 rows per block, 2 blocks/SM ----------------
extern "C" __global__ void __launch_bounds__(NTHR, 2)
fused_kernel(const float* __restrict__ coords,
             const float* __restrict__ ec_g,  const float* __restrict__ ec_b,
             const float* __restrict__ b_pp,
             const float* __restrict__ dg_g,  const float* __restrict__ dg_b,
             float* __restrict__ out)
{
    extern __shared__ float sm[];
    float*    B1       = sm;
    float*    B2       = sm + 4096;
    float*    B3       = sm + 8192;
    float*    pool     = sm;                      // union with B1..B3 + 4096 extra
    float*    s_ecT    = sm + 16384;              // [64][16] = 1024
    float2*   s_act    = (float2*)(sm + 17408);   // 16 x 84 float2 = 2688 floats
    unsigned* s_hist   = (unsigned*)(sm + 20096); // 8 x 256 = 2048
    float*    s_tmp    = sm + 22144;              // 256
    float*    s_bufadd = sm + 22400;              // 64
    float*    s_nov    = sm + 22464;              // 16
    float*    s_red    = sm + 22480;              // 8 warps x 24 = 192

    const int tid  = threadIdx.x;
    const int w    = tid >> 5;
    const int lane = tid & 31;
    const unsigned lmask = (1u << lane) - 1u;
    const int row0 = blockIdx.x * MR;
    const int c0   = tid & 127;          // col pair (c0, c0+128)
    const int rb   = (tid >> 7) * 8;     // row group (0 or 8)
    float* scr = g_scr + (long long)blockIdx.x * (8 * NDG);

    // ---- Stage 0: reduce column partials -> s_bufadd ----
    {
        int c = tid & 63, q = tid >> 6;
        float a = 0.f;
        #pragma unroll 8
        for (int i = 0; i < 64; ++i) a += g_part[(q * 64 + i) * 64 + c];
        s_tmp[q * 64 + c] = a;
        __syncthreads();
        if (tid < 64)
            s_bufadd[tid] = (0.05f / (float)NB) *
                (s_tmp[tid] + s_tmp[64 + tid] + s_tmp[128 + tid] + s_tmp[192 + tid]);
        __syncthreads();
    }

    // ---- Stage 1: EC layernorm (2 rows/warp) -> s_ecT[64][16] ----
    for (int rr = 0; rr < 2; ++rr){
        int r  = w * 2 + rr;
        int gr = row0 + r;
        float v1 = coords[gr*64 + lane]      + s_bufadd[lane];
        float v2 = coords[gr*64 + lane + 32] + s_bufadd[lane + 32];
        float s = v1 + v2, s2 = v1*v1 + v2*v2;
        #pragma unroll
        for (int o = 16; o; o >>= 1){ s += __shfl_xor_sync(~0u, s, o); s2 += __shfl_xor_sync(~0u, s2, o); }
        float mu = s * (1.f/64.f);
        float rs = rsqrtf(s2 * (1.f/64.f) - mu*mu + 1e-5f);
        s_ecT[lane*16 + r]      = (v1 - mu) * rs * ec_g[lane]      + ec_b[lane];
        s_ecT[(lane+32)*16 + r] = (v2 - mu) * rs * ec_g[lane + 32] + ec_b[lane + 32];
    }
    __syncthreads();

    // ---- Stage 2: SINGLE pass over Wpp for all 16 rows; rows 8-15 spill to L2 scratch ----
    {
        const int rq2 = (tid >> 7) * 8;   // this thread's 8 rows: 0-7 or 8-15
        for (int nt = 0; nt < 8; ++nt){
            int ca = nt * 256 + c0, cb = ca + 128;
            u64 a0[4], a1[4];
            u64 bpa = pk2(b_pp[ca]), bpb = pk2(b_pp[cb]);
            #pragma unroll
            for (int q = 0; q < 4; ++q){ a0[q] = bpa; a1[q] = bpb; }
            #pragma unroll 4
            for (int k4 = 0; k4 < 16; ++k4){
                float4 wa = g_Wpp4[k4 * NDG + ca];
                float4 wb = g_Wpp4[k4 * NDG + cb];
                #pragma unroll
                for (int jj = 0; jj < 4; ++jj){
                    const ulonglong2* e = (const ulonglong2*)(s_ecT + (4*k4+jj)*16 + rq2);
                    ulonglong2 v0 = e[0], v1 = e[1];
                    float wA = jj==0?wa.x:jj==1?wa.y:jj==2?wa.z:wa.w;
                    float wB = jj==0?wb.x:jj==1?wb.y:jj==2?wb.z:wb.w;
                    u64 wA2 = pk2(wA), wB2 = pk2(wB);
                    fma2(a0[0], v0.x, wA2); fma2(a0[1], v0.y, wA2);
                    fma2(a0[2], v1.x, wA2); fma2(a0[3], v1.y, wA2);
                    fma2(a1[0], v0.x, wB2); fma2(a1[1], v0.y, wB2);
                    fma2(a1[2], v1.x, wB2); fma2(a1[3], v1.y, wB2);
                }
            }
            float f0[8], f1[8];
            upk(a0[0], f0[0], f0[1]); upk(a0[1], f0[2], f0[3]);
            upk(a0[2], f0[4], f0[5]); upk(a0[3], f0[6], f0[7]);
            upk(a1[0], f1[0], f1[1]); upk(a1[1], f1[2], f1[3]);
            upk(a1[2], f1[4], f1[5]); upk(a1[3], f1[6], f1[7]);
            float* dst = (rq2 == 0) ? pool : scr;
            #pragma unroll
            for (int i = 0; i < 8; ++i){
                dst[i*NDG + ca] = fmaxf(f0[i], 0.f);
                dst[i*NDG + cb] = fmaxf(f1[i], 0.f);
            }
        }
    }
    __syncthreads();

    // ---- Stages 3-4: two select passes (pass 1 reloads rows 8-15 from scratch) ----
    for (int p = 0; p < 2; ++p){
        if (p == 1){
            // reload all 8 rows (16384 floats) from scratch into pool (coalesced float4)
            #pragma unroll
            for (int i = 0; i < 16; ++i){
                int idx = (i * 256 + tid) * 4;
                *(float4*)(pool + idx) = *(const float4*)(scr + idx);
            }
            __syncthreads();
        }

        // 1 row per warp: LN + 3-pass radix (24-bit threshold) + compaction
        {
            unsigned* hist = s_hist + w * 256;
            int rg  = p * 8 + w;
            float* row = pool + w * NDG;
            float s = 0.f, s2 = 0.f;
            for (int i = lane; i < NDG; i += 32){ float v = row[i]; s += v; s2 += v*v; }
            #pragma unroll
            for (int o = 16; o; o >>= 1){ s += __shfl_xor_sync(~0u, s, o); s2 += __shfl_xor_sync(~0u, s2, o); }
            float mu = s * (1.f/2048.f);
            float rs = rsqrtf(s2 * (1.f/2048.f) - mu*mu + 1e-5f);
            for (int i = lane; i < NDG; i += 32)
                row[i] = (row[i] - mu) * rs * dg_g[i] + dg_b[i];
            __syncwarp();

            unsigned prefix = 0; int need = KACT;
            for (int pp = 3; pp >= 1; --pp){
                for (int b = lane; b < 256; b += 32) hist[b] = 0;
                __syncwarp();
                unsigned himask = (pp == 3) ? 0u : (0xFFFFFFFFu << ((pp + 1) * 8));
                for (int i = lane; i < NDG; i += 32){
                    unsigned uu = f2u(row[i]);
                    if ((uu & himask) == prefix) atomicAdd(&hist[(uu >> (pp*8)) & 255], 1u);
                }
                __syncwarp();
                int b0 = 255 - lane * 8;
                unsigned cs[8]; unsigned cnt = 0;
                #pragma unroll
                for (int t = 0; t < 8; ++t){ cs[t] = hist[b0 - t]; cnt += cs[t]; }
                unsigned inc = cnt;
                #pragma unroll
                for (int o = 1; o < 32; o <<= 1){ unsigned v = __shfl_up_sync(~0u, inc, o); if (lane >= o) inc += v; }
                unsigned excl = inc - cnt;
                bool hit = (excl < (unsigned)need) && ((unsigned)need <= inc);
                unsigned bal = __ballot_sync(~0u, hit);
                int srcl = __ffs(bal) - 1;
                int selbin = 0, newneed = 0, found = 0;
                if (hit){
                    unsigned cum = excl;
                    #pragma unroll
                    for (int t = 0; t < 8; ++t){
                        unsigned nc = cum + cs[t];
                        if (!found && nc >= (unsigned)need){ selbin = b0 - t; newneed = need - (int)cum; found = 1; }
                        cum = nc;
                    }
                }
                selbin = __shfl_sync(~0u, selbin, srcl);
                need   = __shfl_sync(~0u, newneed, srcl);
                prefix |= ((unsigned)selbin) << (pp * 8);
            }

            int base = 0, ties = 0;
            for (int g = 0; g < 64; ++g){
                int c = g * 32 + lane;
                float v = row[c];
                unsigned uu = f2u(v) & 0xFFFFFF00u;
                bool eq = (uu == prefix);
                bool gt = (uu >  prefix);
                unsigned beq = __ballot_sync(~0u, eq);
                int tr = ties + __popc(beq & lmask);
                bool act = gt || (eq && tr < need);
                unsigned ba = __ballot_sync(~0u, act);
                if (act){
                    int pos = base + __popc(ba & lmask);
                    s_act[rg*84 + pos] = make_float2(v, __int_as_float(c << 8));
                }
                base += __popc(ba);
                ties += __popc(beq);
            }
        }
        __syncthreads();
    }

    // ---- Stage 5: cue = sparse(dg) @ WmossyT -> B1[256][STR] ----
    {
        float acc[16];
        #pragma unroll
        for (int r = 0; r < 16; ++r) acc[r] = 0.f;
        #pragma unroll 2
        for (int a = 0; a < KACT; ++a){
            #pragma unroll
            for (int r = 0; r < 16; ++r){
                float2 pv = s_act[r*84 + a];
                acc[r] = fmaf(pv.x, g_WmossyT[__float_as_int(pv.y) + tid], acc[r]);
            }
        }
        float4* dp = (float4*)(B1 + tid*STR);
        dp[0] = make_float4(acc[0], acc[1], acc[2], acc[3]);
        dp[1] = make_float4(acc[4], acc[5], acc[6], acc[7]);
        dp[2] = make_float4(acc[8], acc[9], acc[10], acc[11]);
        dp[3] = make_float4(acc[12], acc[13], acc[14], acc[15]);
    }
    __syncthreads();

    // ---- Stage 6: 5-step settle ----
    float cuev[16];
    {
        const float4* ca = (const float4*)(B1 + c0*STR + rb);
        const float4* cb = (const float4*)(B1 + (c0+128)*STR + rb);
        float4 x0 = ca[0], x1 = ca[1], y0 = cb[0], y1 = cb[1];
        cuev[0]=0.6f*x0.x; cuev[1]=0.6f*x0.y; cuev[2]=0.6f*x0.z; cuev[3]=0.6f*x0.w;
        cuev[4]=0.6f*x1.x; cuev[5]=0.6f*x1.y; cuev[6]=0.6f*x1.z; cuev[7]=0.6f*x1.w;
        cuev[8]=0.6f*y0.x; cuev[9]=0.6f*y0.y; cuev[10]=0.6f*y0.z; cuev[11]=0.6f*y0.w;
        cuev[12]=0.6f*y1.x; cuev[13]=0.6f*y1.y; cuev[14]=0.6f*y1.z; cuev[15]=0.6f*y1.w;
    }
    const float* cur = B1;
    float* nxt = B2;
    for (int it = 0; it < 5; ++it){
        u64 acc[8];
        #pragma unroll
        for (int q = 0; q < 8; ++q) acc[q] = 0ull;
        gemv256_u(acc, cur, g_Wrec4, c0, rb);
        float z[16];
        upk8(acc, z);
        float res[16];
        #pragma unroll
        for (int r = 0; r < 16; ++r) res[r] = fast_tanh_z(z[r] + cuev[r]);
        store2x8(nxt, res, c0, rb);
        __syncthreads();
        if (it == 0){ cur = B2; nxt = B3; }
        else { float* t = (float*)cur; cur = nxt; nxt = t; }
    }
    // final state in B2

    // ---- Stages 8+10 fused: 4 GEMVs in 2 paired passes ----
    float fA[16], fB[16];
    {
        u64 acc_s[8], accB[8];
        {
            u64 sa = pk2(g_bcssc[c0]),  sb = pk2(g_bcssc[c0 + 128]);
            u64 oa = pk2(g_b2ogsc[c0]), ob = pk2(g_b2ogsc[c0 + 128]);
            #pragma unroll
            for (int q = 0; q < 4; ++q){
                acc_s[q] = sa; acc_s[q+4] = sb;
                accB[q]  = oa; accB[q+4]  = ob;
            }
        }
        gemv256_pair_u(acc_s, accB, B2, g_Wcssc4, g_Wogsc4, c0, rb);

        u64 acc_d[8], accA[8];
        {
            u64 da = pk2(g_btap[c0]),   db = pk2(g_btap[c0 + 128]);
            u64 oa = pk2(g_b2ogta[c0]), ob = pk2(g_b2ogta[c0 + 128]);
            #pragma unroll
            for (int q = 0; q < 4; ++q){
                acc_d[q] = da; acc_d[q+4] = db;
                accA[q]  = oa; accA[q+4]  = ob;
            }
        }
        gemv64_pair_u(acc_d, accA, s_ecT, g_Wcdta4, g_Wogta4, c0, rb);

        float fs[16], fd[16];
        upk8(acc_s, fs); upk8(acc_d, fd);
        upk8(accA, fA);  upk8(accB, fB);

        #pragma unroll
        for (int i = 0; i < 8; ++i){
            float sd = fs[i]*fd[i] + fs[i+8]*fd[i+8];
            float sn = fs[i]*fs[i] + fs[i+8]*fs[i+8];
            float dn = fd[i]*fd[i] + fd[i+8]*fd[i+8];
            #pragma unroll
            for (int o = 16; o; o >>= 1){
                sd += __shfl_xor_sync(~0u, sd, o);
                sn += __shfl_xor_sync(~0u, sn, o);
                dn += __shfl_xor_sync(~0u, dn, o);
            }
            if (lane == 0){
                s_red[w*24 + i*3 + 0] = sd;
                s_red[w*24 + i*3 + 1] = sn;
                s_red[w*24 + i*3 + 2] = dn;
            }
        }
    }
    __syncthreads();
    if (tid < 16){
        int r = tid, rl = r & 7, wb = (r >> 3) * 4;
        float sd = 0.f, sn = 0.f, dn = 0.f;
        #pragma unroll
        for (int q = 0; q < 4; ++q){
            sd += s_red[(wb+q)*24 + rl*3 + 0];
            sn += s_red[(wb+q)*24 + rl*3 + 1];
            dn += s_red[(wb+q)*24 + rl*3 + 2];
        }
        float s_n = fmaxf(sqrtf(sn), 1e-8f);
        float d_n = fmaxf(sqrtf(dn), 1e-8f);
        float cosv = sd / (s_n * d_n);
        float nov = fminf(fmaxf(1.f - cosv, 0.f), 1.f);
        s_nov[r] = nov;
        out[(long long)NB * NCA + row0 + r] = nov;
    }
    __syncthreads();

    // ---- epilogue: out = tanh( g*A + (1-g)*B ) ----
    {
        float4 g0 = *(const float4*)(s_nov + rb);
        float4 g1 = *(const float4*)(s_nov + rb + 4);
        float gts[8] = {g0.x, g0.y, g0.z, g0.w, g1.x, g1.y, g1.z, g1.w};
        #pragma unroll
        for (int i = 0; i < 8; ++i){
            float g = gts[i];
            float za = fmaf(g, fA[i],   (1.f - g) * fB[i]);
            float zb = fmaf(g, fA[i+8], (1.f - g) * fB[i+8]);
            out[(long long)(row0 + rb + i) * NCA + c0]       = fast_tanh_z(za);
            out[(long long)(row0 + rb + i) * NCA + c0 + 128] = fast_tanh_z(zb);
        }
    }
}

// ---------------- launch ----------------
extern "C" void kernel_launch(void* const* d_in, const int* in_sizes, int n_in,
                              void* d_out, int out_size)
{
    const float* coords = (const float*)d_in[0];
    const float* ec_g   = (const float*)d_in[1];
    const float* ec_b   = (const float*)d_in[2];
    const float* W_pp   = (const float*)d_in[3];
    const float* b_pp   = (const float*)d_in[4];
    const float* dg_g   = (const float*)d_in[5];
    const float* dg_b   = (const float*)d_in[6];
    const float* W_mo   = (const float*)d_in[7];
    const float* W_rec  = (const float*)d_in[8];
    const float* W_sc   = (const float*)d_in[9];
    const float* b_sc   = (const float*)d_in[10];
    const float* W_ta   = (const float*)d_in[11];
    const float* b_ta   = (const float*)d_in[12];
    const float* W_cs   = (const float*)d_in[13];
    const float* W_cd   = (const float*)d_in[14];
    const float* W_og   = (const float*)d_in[15];
    const float* b_og   = (const float*)d_in[16];
    float* out = (float*)d_out;

    const size_t smem = (size_t)(16384 + 1024 + 2688 + 2048 + 256 + 64 + 16 + 192) * 4;  // 90,688 B
    static int configured = 0;
    if (!configured){
        cudaFuncSetAttribute(fused_kernel, cudaFuncAttributeMaxDynamicSharedMemorySize, (int)smem);
        configured = 1;
    }

    prep_kernel<<<896, 256>>>(coords, W_pp, W_mo, W_rec);
    prep_gemm<<<164, 256>>>(W_cs, W_cd, W_og, W_sc, W_ta, b_ta, b_sc, b_og);
    fused_kernel<<<NB / MR, NTHR, smem>>>(coords, ec_g, ec_b, b_pp, dg_g, dg_b, out);
}

// round 17
// speedup vs baseline: 1.0795x; 1.0089x over previous
#include <cuda_runtime.h>

#define NB   32768
#define NCO  64
#define NDG  2048
#define NCA  256
#define KACT 81
#define MR   16
#define NTHR 256
#define STR  16   // float stride of [256 col][16 row] tiles

typedef unsigned long long u64;

// ---------------- device-global scratch ----------------
__device__ float4 g_Wpp4[16 * NDG];      // [k4][c]
__device__ float  g_WmossyT[NDG * NCA];  // [d][c]
__device__ float4 g_Wrec4[64 * NCA];     // [j4][c], pre-scaled by 1.4 (=2*GAIN)
__device__ float4 g_Wcssc4[64 * NCA];    // (Wcs @ Wsc)
__device__ float4 g_Wogsc4[64 * NCA];    // 2*(Wog @ Wsc)
__device__ float4 g_Wogta4[16 * NCA];    // 2*(Wog @ Wta)
__device__ float4 g_Wcdta4[16 * NCA];    // (Wcd @ Wta)
__device__ float  g_btap[NCA];           // Wcd @ b_ta
__device__ float  g_bcssc[NCA];          // Wcs @ b_sc
__device__ float  g_b2ogta[NCA];         // 2*(Wog @ b_ta) + 2*b_og
__device__ float  g_b2ogsc[NCA];         // 2*(Wog @ b_sc) + 2*b_og
__device__ float  g_part[256 * NCO];
__device__ float  g_bufadd[NCO];         // 0.05 * column mean (final)
__device__ float  g_scr[(long long)2048 * 8 * NDG];  // proj rows 8-15 spill (L2-resident)

// ---------------- f32x2 packed helpers ----------------
__device__ __forceinline__ u64 pk2(float v){
    u64 r; asm("mov.b64 %0, {%1, %1};" : "=l"(r) : "f"(v)); return r;
}
__device__ __forceinline__ void upk(u64 p, float& a, float& b){
    asm("mov.b64 {%0, %1}, %2;" : "=f"(a), "=f"(b) : "l"(p));
}
__device__ __forceinline__ void fma2(u64& acc, u64 v, u64 w){
    asm("fma.rn.f32x2 %0, %1, %2, %0;" : "+l"(acc) : "l"(v), "l"(w));
}

// order-preserving float->uint key
__device__ __forceinline__ unsigned f2u(float f){
    unsigned u = __float_as_uint(f);
    return u ^ ((u & 0x80000000u) ? 0xFFFFFFFFu : 0x80000000u);
}

// tanh where z = 2x is already applied
__device__ __forceinline__ float fast_tanh_z(float z){
    float e = __expf(z);
    return 1.f - __fdividef(2.f, e + 1.f);
}

// 2 cols x 8 rows packed: acc[0..3]=colA row-pairs, acc[4..7]=colB
__device__ __forceinline__ void fma2x8_u(u64 acc[8], const float* __restrict__ sT,
                                         u64 wA, u64 wB){
    const ulonglong2* e = (const ulonglong2*)sT;
    ulonglong2 v0 = e[0], v1 = e[1];
    fma2(acc[0], v0.x, wA); fma2(acc[1], v0.y, wA);
    fma2(acc[2], v1.x, wA); fma2(acc[3], v1.y, wA);
    fma2(acc[4], v0.x, wB); fma2(acc[5], v0.y, wB);
    fma2(acc[6], v1.x, wB); fma2(acc[7], v1.y, wB);
}

__device__ __forceinline__ void fma2x8_pair_u(u64 P[8], u64 Q[8],
                                              const float* __restrict__ sT,
                                              u64 pA, u64 pB, u64 qA, u64 qB){
    const ulonglong2* e = (const ulonglong2*)sT;
    ulonglong2 v0 = e[0], v1 = e[1];
    fma2(P[0], v0.x, pA); fma2(P[1], v0.y, pA);
    fma2(P[2], v1.x, pA); fma2(P[3], v1.y, pA);
    fma2(P[4], v0.x, pB); fma2(P[5], v0.y, pB);
    fma2(P[6], v1.x, pB); fma2(P[7], v1.y, pB);
    fma2(Q[0], v0.x, qA); fma2(Q[1], v0.y, qA);
    fma2(Q[2], v1.x, qA); fma2(Q[3], v1.y, qA);
    fma2(Q[4], v0.x, qB); fma2(Q[5], v0.y, qB);
    fma2(Q[6], v1.x, qB); fma2(Q[7], v1.y, qB);
}

// GEMV over 256 inputs
__device__ __forceinline__ void gemv256_u(u64 acc[8], const float* __restrict__ src,
                                          const float4* __restrict__ w4, int c0, int rb){
    #pragma unroll 4
    for (int j4 = 0; j4 < 64; ++j4){
        float4 wa = w4[j4 * NCA + c0];
        float4 wb = w4[j4 * NCA + c0 + 128];
        fma2x8_u(acc, src + (4*j4+0)*STR + rb, pk2(wa.x), pk2(wb.x));
        fma2x8_u(acc, src + (4*j4+1)*STR + rb, pk2(wa.y), pk2(wb.y));
        fma2x8_u(acc, src + (4*j4+2)*STR + rb, pk2(wa.z), pk2(wb.z));
        fma2x8_u(acc, src + (4*j4+3)*STR + rb, pk2(wa.w), pk2(wb.w));
    }
}

__device__ __forceinline__ void gemv256_pair_u(u64 P[8], u64 Q[8],
                                               const float* __restrict__ src,
                                               const float4* __restrict__ wp,
                                               const float4* __restrict__ wq,
                                               int c0, int rb){
    #pragma unroll 2
    for (int j4 = 0; j4 < 64; ++j4){
        float4 pa = wp[j4 * NCA + c0];
        float4 pb = wp[j4 * NCA + c0 + 128];
        float4 qa = wq[j4 * NCA + c0];
        float4 qb = wq[j4 * NCA + c0 + 128];
        fma2x8_pair_u(P, Q, src + (4*j4+0)*STR + rb, pk2(pa.x), pk2(pb.x), pk2(qa.x), pk2(qb.x));
        fma2x8_pair_u(P, Q, src + (4*j4+1)*STR + rb, pk2(pa.y), pk2(pb.y), pk2(qa.y), pk2(qb.y));
        fma2x8_pair_u(P, Q, src + (4*j4+2)*STR + rb, pk2(pa.z), pk2(pb.z), pk2(qa.z), pk2(qb.z));
        fma2x8_pair_u(P, Q, src + (4*j4+3)*STR + rb, pk2(pa.w), pk2(pb.w), pk2(qa.w), pk2(qb.w));
    }
}

// paired GEMV over 64 inputs (reads s_ecT [64][16])
__device__ __forceinline__ void gemv64_pair_u(u64 P[8], u64 Q[8],
                                              const float* __restrict__ src,
                                              const float4* __restrict__ wp,
                                              const float4* __restrict__ wq,
                                              int c0, int rb){
    #pragma unroll 2
    for (int k4 = 0; k4 < 16; ++k4){
        float4 pa = wp[k4 * NCA + c0];
        float4 pb = wp[k4 * NCA + c0 + 128];
        float4 qa = wq[k4 * NCA + c0];
        float4 qb = wq[k4 * NCA + c0 + 128];
        fma2x8_pair_u(P, Q, src + (4*k4+0)*16 + rb, pk2(pa.x), pk2(pb.x), pk2(qa.x), pk2(qb.x));
        fma2x8_pair_u(P, Q, src + (4*k4+1)*16 + rb, pk2(pa.y), pk2(pb.y), pk2(qa.y), pk2(qb.y));
        fma2x8_pair_u(P, Q, src + (4*k4+2)*16 + rb, pk2(pa.z), pk2(pb.z), pk2(qa.z), pk2(qb.z));
        fma2x8_pair_u(P, Q, src + (4*k4+3)*16 + rb, pk2(pa.w), pk2(pb.w), pk2(qa.w), pk2(qb.w));
    }
}

__device__ __forceinline__ void store2x8(float* __restrict__ dst, const float acc[16],
                                         int c0, int rb){
    float4* d0 = (float4*)(dst + c0*STR + rb);
    float4* d1 = (float4*)(dst + (c0+128)*STR + rb);
    d0[0] = make_float4(acc[0], acc[1], acc[2], acc[3]);
    d0[1] = make_float4(acc[4], acc[5], acc[6], acc[7]);
    d1[0] = make_float4(acc[8], acc[9], acc[10], acc[11]);
    d1[1] = make_float4(acc[12], acc[13], acc[14], acc[15]);
}

// unpack 8 packed accs: [0..7]=first set rows, [8..15]=second set rows
__device__ __forceinline__ void upk8(const u64 acc[8], float out[16]){
    upk(acc[0], out[0],  out[1]);  upk(acc[1], out[2],  out[3]);
    upk(acc[2], out[4],  out[5]);  upk(acc[3], out[6],  out[7]);
    upk(acc[4], out[8],  out[9]);  upk(acc[5], out[10], out[11]);
    upk(acc[6], out[12], out[13]); upk(acc[7], out[14], out[15]);
}

// ---------------- prep kernel: coalesced relayouts + column partial sums ----------------
__global__ void prep_kernel(const float* __restrict__ coords,
                            const float* __restrict__ W_pp, const float* __restrict__ W_mo,
                            const float* __restrict__ W_rec)
{
    __shared__ float sh[32 * 65];
    const int b = blockIdx.x, tid = threadIdx.x;
    const int tx = tid & 31, ty = tid >> 5;

    if (b < 256){
        __shared__ float s[4][64];
        int c = tid & 63, g = tid >> 6;
        int r0 = b * 128 + g * 32;
        float acc = 0.f;
        #pragma unroll 8
        for (int i = 0; i < 32; ++i) acc += coords[(r0 + i) * 64 + c];
        s[g][c] = acc;
        __syncthreads();
        if (g == 0) g_part[b * 64 + c] = s[0][c] + s[1][c] + s[2][c] + s[3][c];
    } else if (b < 768){
        int b2 = b - 256;
        int ci = b2 & 7, di = b2 >> 3;
        #pragma unroll
        for (int i = 0; i < 4; ++i){
            int cc = ty + 8 * i;
            sh[cc * 33 + tx] = W_mo[(ci * 32 + cc) * 2048 + di * 32 + tx];
        }
        __syncthreads();
        #pragma unroll
        for (int i = 0; i < 4; ++i){
            int dd = ty + 8 * i;
            g_WmossyT[(di * 32 + dd) * 256 + ci * 32 + tx] = sh[tx * 33 + dd];
        }
    } else if (b < 832){
        int c0 = (b - 768) * 32;
        #pragma unroll
        for (int i = 0; i < 8; ++i){
            int idx = i * 256 + tid;
            int row = idx >> 6, col = idx & 63;
            sh[row * 65 + col] = W_pp[(c0 + row) * 64 + col];
        }
        __syncthreads();
        #pragma unroll
        for (int oi = 0; oi < 2; ++oi){
            int idx = oi * 256 + tid;
            int k4 = idx >> 5, c = idx & 31;
            float4 v = make_float4(sh[c * 65 + 4*k4], sh[c * 65 + 4*k4 + 1],
                                   sh[c * 65 + 4*k4 + 2], sh[c * 65 + 4*k4 + 3]);
            g_Wpp4[k4 * NDG + c0 + c] = v;
        }
    } else {
        int b4 = b - 832;
        int ci = b4 & 7, ji = b4 >> 3;
        #pragma unroll
        for (int i = 0; i < 4; ++i){
            int cc = ty + 8 * i;
            sh[cc * 33 + tx] = W_rec[(ci * 32 + cc) * 256 + ji * 32 + tx];
        }
        __syncthreads();
        {
            int j4l = ty, c = tx;
            float4 v = make_float4(1.4f * sh[c * 33 + 4*j4l],     1.4f * sh[c * 33 + 4*j4l + 1],
                                   1.4f * sh[c * 33 + 4*j4l + 2], 1.4f * sh[c * 33 + 4*j4l + 3]);
            g_Wrec4[(ji * 8 + j4l) * NCA + ci * 32 + c] = v;
        }
    }
}

// ---------------- tiled GEMM prep + bias dots + bufadd reduce ----------------
__global__ void prep_gemm(const float* __restrict__ W_cs, const float* __restrict__ W_cd,
                          const float* __restrict__ W_og,
                          const float* __restrict__ W_sc, const float* __restrict__ W_ta,
                          const float* __restrict__ b_ta, const float* __restrict__ b_sc,
                          const float* __restrict__ b_og)
{
    int b = blockIdx.x;
    int tx = threadIdx.x & 31;
    int ty = threadIdx.x >> 5;

    if (b == 164){
        // final bufadd reduce (prep_kernel already ran, stream-ordered)
        int c = threadIdx.x & 63, q = threadIdx.x >> 6;
        __shared__ float s_t[256];
        float a = 0.f;
        #pragma unroll 8
        for (int i = 0; i < 64; ++i) a += g_part[(q * 64 + i) * 64 + c];
        s_t[q * 64 + c] = a;
        __syncthreads();
        if (threadIdx.x < 64)
            g_bufadd[threadIdx.x] = (0.05f / (float)NB) *
                (s_t[threadIdx.x] + s_t[64 + threadIdx.x] +
                 s_t[128 + threadIdx.x] + s_t[192 + threadIdx.x]);
        return;
    }
    if (b >= 160){
        int t = b - 160;
        const float* A   = (t==0) ? W_cd : (t==1) ? W_cs : W_og;
        const float* vec = (t==0) ? b_ta : (t==1) ? b_sc : (t==2) ? b_ta : b_sc;
        float* dst = (t==0) ? g_btap : (t==1) ? g_bcssc : (t==2) ? g_b2ogta : g_b2ogsc;
        float scale = (t < 2) ? 1.f : 2.f;
        for (int c = ty; c < 256; c += 8){
            float acc = 0.f;
            #pragma unroll
            for (int kt = 0; kt < 8; ++kt)
                acc = fmaf(A[c * 256 + kt * 32 + tx], vec[kt * 32 + tx], acc);
            #pragma unroll
            for (int o = 16; o; o >>= 1) acc += __shfl_xor_sync(~0u, acc, o);
            if (tx == 0) dst[c] = scale * acc + ((t >= 2) ? 2.f * b_og[c] : 0.f);
        }
        return;
    }

    __shared__ float As[32][33];
    __shared__ float Bs[32][33];

    const float *A, *B; float* dst; float scale; int ldb, jtiles;
    if (b < 64)      { A = W_cs; B = W_sc; dst = (float*)g_Wcssc4; scale = 1.f; ldb = 256; jtiles = 8; }
    else if (b < 128){ A = W_og; B = W_sc; dst = (float*)g_Wogsc4; scale = 2.f; ldb = 256; jtiles = 8; b -= 64; }
    else if (b < 144){ A = W_og; B = W_ta; dst = (float*)g_Wogta4; scale = 2.f; ldb = 64;  jtiles = 2; b -= 128; }
    else             { A = W_cd; B = W_ta; dst = (float*)g_Wcdta4; scale = 1.f; ldb = 64;  jtiles = 2; b -= 144; }

    int ci = b / jtiles, ji = b % jtiles;
    float acc[4] = {0.f, 0.f, 0.f, 0.f};
    for (int kt = 0; kt < 8; ++kt){
        #pragma unroll
        for (int ii = 0; ii < 4; ++ii){
            int rr = ty + 8 * ii;
            As[rr][tx] = A[(ci * 32 + rr) * 256 + kt * 32 + tx];
            Bs[rr][tx] = B[(kt * 32 + rr) * ldb + ji * 32 + tx];
        }
        __syncthreads();
        #pragma unroll
        for (int kk = 0; kk < 32; ++kk){
            float bv = Bs[kk][tx];
            #pragma unroll
            for (int ii = 0; ii < 4; ++ii)
                acc[ii] = fmaf(As[ty + 8 * ii][kk], bv, acc[ii]);
        }
        __syncthreads();
    }

    #pragma unroll
    for (int ii = 0; ii < 4; ++ii)
        As[ty + 8 * ii][tx] = scale * acc[ii];
    __syncthreads();
    {
        int j4l = ty, cl = tx;
        int j0 = ji * 32 + j4l * 4;
        float4 v = make_float4(As[cl][j4l*4], As[cl][j4l*4+1], As[cl][j4l*4+2], As[cl][j4l*4+3]);
        ((float4*)dst)[(j0 >> 2) * NCA + ci * 32 + cl] = v;
    }
}

// ---------------- fused pipeline: 16 rows per block, 2 blocks/SM ----------------
extern "C" __global__ void __launch_bounds__(NTHR, 2)
fused_kernel(const float* __restrict__ coords,
             const float* __restrict__ ec_g,  const float* __restrict__ ec_b,
             const float* __restrict__ b_pp,
             const float* __restrict__ dg_g,  const float* __restrict__ dg_b,
             float* __restrict__ out)
{
    extern __shared__ float sm[];
    float*    B1       = sm;
    float*    B2       = sm + 4096;
    float*    B3       = sm + 8192;
    float*    pool     = sm;                      // union with B1..B3 + 4096 extra
    float*    s_ecT    = sm + 16384;              // [64][16] = 1024
    float2*   s_act    = (float2*)(sm + 17408);   // 16 x 84 float2 = 2688 floats
    unsigned* s_hist   = (unsigned*)(sm + 20096); // 8 x 256 = 2048
    float*    s_bufadd = sm + 22144;              // 64
    float*    s_nov    = sm + 22208;              // 16
    float*    s_red    = sm + 22224;              // 8 warps x 24 = 192

    const int tid  = threadIdx.x;
    const int w    = tid >> 5;
    const int lane = tid & 31;
    const unsigned lmask = (1u << lane) - 1u;
    const int row0 = blockIdx.x * MR;
    const int c0   = tid & 127;          // col pair (c0, c0+128)
    const int rb   = (tid >> 7) * 8;     // row group (0 or 8)
    float* scr = g_scr + (long long)blockIdx.x * (8 * NDG);

    // ---- Stage 0: load precomputed bufadd ----
    if (tid < 64) s_bufadd[tid] = g_bufadd[tid];
    __syncthreads();

    // ---- Stage 1: EC layernorm (2 rows/warp) -> s_ecT[64][16] ----
    for (int rr = 0; rr < 2; ++rr){
        int r  = w * 2 + rr;
        int gr = row0 + r;
        float v1 = coords[gr*64 + lane]      + s_bufadd[lane];
        float v2 = coords[gr*64 + lane + 32] + s_bufadd[lane + 32];
        float s = v1 + v2, s2 = v1*v1 + v2*v2;
        #pragma unroll
        for (int o = 16; o; o >>= 1){ s += __shfl_xor_sync(~0u, s, o); s2 += __shfl_xor_sync(~0u, s2, o); }
        float mu = s * (1.f/64.f);
        float rs = rsqrtf(s2 * (1.f/64.f) - mu*mu + 1e-5f);
        s_ecT[lane*16 + r]      = (v1 - mu) * rs * ec_g[lane]      + ec_b[lane];
        s_ecT[(lane+32)*16 + r] = (v2 - mu) * rs * ec_g[lane + 32] + ec_b[lane + 32];
    }
    __syncthreads();

    // ---- Stage 2: SINGLE pass over Wpp for all 16 rows; rows 8-15 spill to L2 scratch ----
    {
        const int rq2 = (tid >> 7) * 8;
        for (int nt = 0; nt < 8; ++nt){
            int ca = nt * 256 + c0, cb = ca + 128;
            u64 a0[4], a1[4];
            u64 bpa = pk2(b_pp[ca]), bpb = pk2(b_pp[cb]);
            #pragma unroll
            for (int q = 0; q < 4; ++q){ a0[q] = bpa; a1[q] = bpb; }
            #pragma unroll 4
            for (int k4 = 0; k4 < 16; ++k4){
                float4 wa = g_Wpp4[k4 * NDG + ca];
                float4 wb = g_Wpp4[k4 * NDG + cb];
                #pragma unroll
                for (int jj = 0; jj < 4; ++jj){
                    const ulonglong2* e = (const ulonglong2*)(s_ecT + (4*k4+jj)*16 + rq2);
                    ulonglong2 v0 = e[0], v1 = e[1];
                    float wA = jj==0?wa.x:jj==1?wa.y:jj==2?wa.z:wa.w;
                    float wB = jj==0?wb.x:jj==1?wb.y:jj==2?wb.z:wb.w;
                    u64 wA2 = pk2(wA), wB2 = pk2(wB);
                    fma2(a0[0], v0.x, wA2); fma2(a0[1], v0.y, wA2);
                    fma2(a0[2], v1.x, wA2); fma2(a0[3], v1.y, wA2);
                    fma2(a1[0], v0.x, wB2); fma2(a1[1], v0.y, wB2);
                    fma2(a1[2], v1.x, wB2); fma2(a1[3], v1.y, wB2);
                }
            }
            float f0[8], f1[8];
            upk(a0[0], f0[0], f0[1]); upk(a0[1], f0[2], f0[3]);
            upk(a0[2], f0[4], f0[5]); upk(a0[3], f0[6], f0[7]);
            upk(a1[0], f1[0], f1[1]); upk(a1[1], f1[2], f1[3]);
            upk(a1[2], f1[4], f1[5]); upk(a1[3], f1[6], f1[7]);
            float* dst = (rq2 == 0) ? pool : scr;
            #pragma unroll
            for (int i = 0; i < 8; ++i){
                dst[i*NDG + ca] = fmaxf(f0[i], 0.f);
                dst[i*NDG + cb] = fmaxf(f1[i], 0.f);
            }
        }
    }
    __syncthreads();

    // ---- Stages 3-4: two select passes (pass 1 reloads rows 8-15 from scratch) ----
    for (int p = 0; p < 2; ++p){
        if (p == 1){
            #pragma unroll
            for (int i = 0; i < 16; ++i){
                int idx = (i * 256 + tid) * 4;
                *(float4*)(pool + idx) = *(const float4*)(scr + idx);
            }
            __syncthreads();
        }

        // 1 row per warp: LN stats + (LN-rewrite fused into hist pass 3) + 2 more hist + compaction
        {
            unsigned* hist = s_hist + w * 256;
            int rg  = p * 8 + w;
            float* row = pool + w * NDG;
            float s = 0.f, s2 = 0.f;
            for (int i = lane; i < NDG; i += 32){ float v = row[i]; s += v; s2 += v*v; }
            #pragma unroll
            for (int o = 16; o; o >>= 1){ s += __shfl_xor_sync(~0u, s, o); s2 += __shfl_xor_sync(~0u, s2, o); }
            float mu = s * (1.f/2048.f);
            float rs = rsqrtf(s2 * (1.f/2048.f) - mu*mu + 1e-5f);

            // pass 3 histogram fused with LN rewrite (numerically identical to separate passes)
            for (int bb = lane; bb < 256; bb += 32) hist[bb] = 0;
            __syncwarp();
            for (int i = lane; i < NDG; i += 32){
                float v = (row[i] - mu) * rs * dg_g[i] + dg_b[i];
                row[i] = v;
                atomicAdd(&hist[f2u(v) >> 24], 1u);
            }
            __syncwarp();

            unsigned prefix = 0; int need = KACT;
            for (int pp = 3; pp >= 1; --pp){
                if (pp != 3){
                    for (int bb = lane; bb < 256; bb += 32) hist[bb] = 0;
                    __syncwarp();
                    unsigned himask = 0xFFFFFFFFu << ((pp + 1) * 8);
                    for (int i = lane; i < NDG; i += 32){
                        unsigned uu = f2u(row[i]);
                        if ((uu & himask) == prefix) atomicAdd(&hist[(uu >> (pp*8)) & 255], 1u);
                    }
                    __syncwarp();
                }
                int b0 = 255 - lane * 8;
                unsigned cs[8]; unsigned cnt = 0;
                #pragma unroll
                for (int t = 0; t < 8; ++t){ cs[t] = hist[b0 - t]; cnt += cs[t]; }
                unsigned inc = cnt;
                #pragma unroll
                for (int o = 1; o < 32; o <<= 1){ unsigned v = __shfl_up_sync(~0u, inc, o); if (lane >= o) inc += v; }
                unsigned excl = inc - cnt;
                bool hit = (excl < (unsigned)need) && ((unsigned)need <= inc);
                unsigned bal = __ballot_sync(~0u, hit);
                int srcl = __ffs(bal) - 1;
                int selbin = 0, newneed = 0, found = 0;
                if (hit){
                    unsigned cum = excl;
                    #pragma unroll
                    for (int t = 0; t < 8; ++t){
                        unsigned nc = cum + cs[t];
                        if (!found && nc >= (unsigned)need){ selbin = b0 - t; newneed = need - (int)cum; found = 1; }
                        cum = nc;
                    }
                }
                selbin = __shfl_sync(~0u, selbin, srcl);
                need   = __shfl_sync(~0u, newneed, srcl);
                prefix |= ((unsigned)selbin) << (pp * 8);
            }

            int base = 0, ties = 0;
            for (int g = 0; g < 64; ++g){
                int c = g * 32 + lane;
                float v = row[c];
                unsigned uu = f2u(v) & 0xFFFFFF00u;
                bool eq = (uu == prefix);
                bool gt = (uu >  prefix);
                unsigned beq = __ballot_sync(~0u, eq);
                int tr = ties + __popc(beq & lmask);
                bool act = gt || (eq && tr < need);
                unsigned ba = __ballot_sync(~0u, act);
                if (act){
                    int pos = base + __popc(ba & lmask);
                    s_act[rg*84 + pos] = make_float2(v, __int_as_float(c << 8));
                }
                base += __popc(ba);
                ties += __popc(beq);
            }
        }
        __syncthreads();
    }

    // ---- Stage 5: cue = sparse(dg) @ WmossyT -> B1[256][STR] (raw, R15-exact) ----
    {
        float acc[16];
        #pragma unroll
        for (int r = 0; r < 16; ++r) acc[r] = 0.f;
        #pragma unroll 2
        for (int a = 0; a < KACT; ++a){
            #pragma unroll
            for (int r = 0; r < 16; ++r){
                float2 pv = s_act[r*84 + a];
                acc[r] = fmaf(pv.x, g_WmossyT[__float_as_int(pv.y) + tid], acc[r]);
            }
        }
        float4* dp = (float4*)(B1 + tid*STR);
        dp[0] = make_float4(acc[0], acc[1], acc[2], acc[3]);
        dp[1] = make_float4(acc[4], acc[5], acc[6], acc[7]);
        dp[2] = make_float4(acc[8], acc[9], acc[10], acc[11]);
        dp[3] = make_float4(acc[12], acc[13], acc[14], acc[15]);
    }
    __syncthreads();

    // ---- Stage 6: 5-step settle (R15-exact: cuev = 0.6 * raw cue) ----
    float cuev[16];
    {
        const float4* ca = (const float4*)(B1 + c0*STR + rb);
        const float4* cb = (const float4*)(B1 + (c0+128)*STR + rb);
        float4 x0 = ca[0], x1 = ca[1], y0 = cb[0], y1 = cb[1];
        cuev[0]=0.6f*x0.x; cuev[1]=0.6f*x0.y; cuev[2]=0.6f*x0.z; cuev[3]=0.6f*x0.w;
        cuev[4]=0.6f*x1.x; cuev[5]=0.6f*x1.y; cuev[6]=0.6f*x1.z; cuev[7]=0.6f*x1.w;
        cuev[8]=0.6f*y0.x; cuev[9]=0.6f*y0.y; cuev[10]=0.6f*y0.z; cuev[11]=0.6f*y0.w;
        cuev[12]=0.6f*y1.x; cuev[13]=0.6f*y1.y; cuev[14]=0.6f*y1.z; cuev[15]=0.6f*y1.w;
    }
    const float* cur = B1;
    float* nxt = B2;
    for (int it = 0; it < 5; ++it){
        u64 acc[8];
        #pragma unroll
        for (int q = 0; q < 8; ++q) acc[q] = 0ull;
        gemv256_u(acc, cur, g_Wrec4, c0, rb);
        float z[16];
        upk8(acc, z);
        float res[16];
        #pragma unroll
        for (int r = 0; r < 16; ++r) res[r] = fast_tanh_z(z[r] + cuev[r]);
        store2x8(nxt, res, c0, rb);
        __syncthreads();
        if (it == 0){ cur = B2; nxt = B3; }
        else { float* t = (float*)cur; cur = nxt; nxt = t; }
    }
    // final state in B2

    // ---- Stages 8+10 fused: 4 GEMVs in 2 paired passes ----
    float fA[16], fB[16];
    {
        u64 acc_s[8], accB[8];
        {
            u64 sa = pk2(g_bcssc[c0]),  sb = pk2(g_bcssc[c0 + 128]);
            u64 oa = pk2(g_b2ogsc[c0]), ob = pk2(g_b2ogsc[c0 + 128]);
            #pragma unroll
            for (int q = 0; q < 4; ++q){
                acc_s[q] = sa; acc_s[q+4] = sb;
                accB[q]  = oa; accB[q+4]  = ob;
            }
        }
        gemv256_pair_u(acc_s, accB, B2, g_Wcssc4, g_Wogsc4, c0, rb);

        u64 acc_d[8], accA[8];
        {
            u64 da = pk2(g_btap[c0]),   db = pk2(g_btap[c0 + 128]);
            u64 oa = pk2(g_b2ogta[c0]), ob = pk2(g_b2ogta[c0 + 128]);
            #pragma unroll
            for (int q = 0; q < 4; ++q){
                acc_d[q] = da; acc_d[q+4] = db;
                accA[q]  = oa; accA[q+4]  = ob;
            }
        }
        gemv64_pair_u(acc_d, accA, s_ecT, g_Wcdta4, g_Wogta4, c0, rb);

        float fs[16], fd[16];
        upk8(acc_s, fs); upk8(acc_d, fd);
        upk8(accA, fA);  upk8(accB, fB);

        #pragma unroll
        for (int i = 0; i < 8; ++i){
            float sd = fs[i]*fd[i] + fs[i+8]*fd[i+8];
            float sn = fs[i]*fs[i] + fs[i+8]*fs[i+8];
            float dn = fd[i]*fd[i] + fd[i+8]*fd[i+8];
            #pragma unroll
            for (int o = 16; o; o >>= 1){
                sd += __shfl_xor_sync(~0u, sd, o);
                sn += __shfl_xor_sync(~0u, sn, o);
                dn += __shfl_xor_sync(~0u, dn, o);
            }
            if (lane == 0){
                s_red[w*24 + i*3 + 0] = sd;
                s_red[w*24 + i*3 + 1] = sn;
                s_red[w*24 + i*3 + 2] = dn;
            }
        }
    }
    __syncthreads();
    if (tid < 16){
        int r = tid, rl = r & 7, wb = (r >> 3) * 4;
        float sd = 0.f, sn = 0.f, dn = 0.f;
        #pragma unroll
        for (int q = 0; q < 4; ++q){
            sd += s_red[(wb+q)*24 + rl*3 + 0];
            sn += s_red[(wb+q)*24 + rl*3 + 1];
            dn += s_red[(wb+q)*24 + rl*3 + 2];
        }
        float s_n = fmaxf(sqrtf(sn), 1e-8f);
        float d_n = fmaxf(sqrtf(dn), 1e-8f);
        float cosv = sd / (s_n * d_n);
        float nov = fminf(fmaxf(1.f - cosv, 0.f), 1.f);
        s_nov[r] = nov;
        out[(long long)NB * NCA + row0 + r] = nov;
    }
    __syncthreads();

    // ---- epilogue: out = tanh( g*A + (1-g)*B ) ----
    {
        float4 g0 = *(const float4*)(s_nov + rb);
        float4 g1 = *(const float4*)(s_nov + rb + 4);
        float gts[8] = {g0.x, g0.y, g0.z, g0.w, g1.x, g1.y, g1.z, g1.w};
        #pragma unroll
        for (int i = 0; i < 8; ++i){
            float g = gts[i];
            float za = fmaf(g, fA[i],   (1.f - g) * fB[i]);
            float zb = fmaf(g, fA[i+8], (1.f - g) * fB[i+8]);
            out[(long long)(row0 + rb + i) * NCA + c0]       = fast_tanh_z(za);
            out[(long long)(row0 + rb + i) * NCA + c0 + 128] = fast_tanh_z(zb);
        }
    }
}

// ---------------- launch ----------------
extern "C" void kernel_launch(void* const* d_in, const int* in_sizes, int n_in,
                              void* d_out, int out_size)
{
    const float* coords = (const float*)d_in[0];
    const float* ec_g   = (const float*)d_in[1];
    const float* ec_b   = (const float*)d_in[2];
    const float* W_pp   = (const float*)d_in[3];
    const float* b_pp   = (const float*)d_in[4];
    const float* dg_g   = (const float*)d_in[5];
    const float* dg_b   = (const float*)d_in[6];
    const float* W_mo   = (const float*)d_in[7];
    const float* W_rec  = (const float*)d_in[8];
    const float* W_sc   = (const float*)d_in[9];
    const float* b_sc   = (const float*)d_in[10];
    const float* W_ta   = (const float*)d_in[11];
    const float* b_ta   = (const float*)d_in[12];
    const float* W_cs   = (const float*)d_in[13];
    const float* W_cd   = (const float*)d_in[14];
    const float* W_og   = (const float*)d_in[15];
    const float* b_og   = (const float*)d_in[16];
    float* out = (float*)d_out;

    // smem floats: union 16384 + ecT 1024 + act 2688 + hist 2048 + bufadd 64 + nov 16 + red 192
    const size_t smem = (size_t)(16384 + 1024 + 2688 + 2048 + 64 + 16 + 192) * 4;  // 89,664 B
    static int configured = 0;
    if (!configured){
        cudaFuncSetAttribute(fused_kernel, cudaFuncAttributeMaxDynamicSharedMemorySize, (int)smem);
        configured = 1;
    }

    prep_kernel<<<896, 256>>>(coords, W_pp, W_mo, W_rec);
    prep_gemm<<<165, 256>>>(W_cs, W_cd, W_og, W_sc, W_ta, b_ta, b_sc, b_og);
    fused_kernel<<<NB / MR, NTHR, smem>>>(coords, ec_g, ec_b, b_pp, dg_g, dg_b, out);
}